// round 17
// baseline (speedup 1.0000x reference)
#include <cuda_runtime.h>
#include <cuda_bf16.h>
#include <cstdint>
#include <math.h>

// ---------------------------------------------------------------------------
// Binary CNN fused. Round 17: IMMA version, A-operand off-by-one FIXED
// (stage-C K window starts at padded row w = half*16+g, not +1).
//  - stages C/D on tensor pipe via mma.sync.m16n8k32.s8 (exact s32 accum)
//  - stage B emits +-1 s8 bytes, act[h][w+1][cin]; pad rows zero
//  - BN sign mu folded into weight bytes -> bit = (d' >= T)
// All integer-exact: rel_err must stay 0.0.
// ---------------------------------------------------------------------------

#define EPSBND 1e-5
#define BAND   1e-3f

__device__ float    g_w1s[32 * 9];
__device__ double   g_inv1d[32], g_bz1d[32], g_b1d[32];
__device__ float2   g_p1[32];
__device__ __align__(16) unsigned g_wb2[64 * 4];   // stage B bits, sign-folded
__device__ int2     g_kB[64];                      // (K96, K64)
__device__ __align__(16) signed char g_wCb[128 * 192];  // [ch][tap*64+cin], mu-folded
__device__ int      g_TC[128];
__device__ __align__(16) signed char g_wDb[128 * 768];  // [ch][h*128+cin], mu-folded
__device__ int      g_TD[128];
__device__ unsigned g_wfb[10 * 64];

__device__ __forceinline__ float bnref(float dv, float bias, float inv, float bz) {
    return __fadd_rn(__fmul_rn(__fadd_rn(dv, bias), inv), bz);
}

// bit(d) = (mu*d >= T) matching (bnref(d) >= 0) over integer d.
__device__ void mk_threshold(float b, float g, float be, float m, float v,
                             int* mu_out, int* T_out)
{
    float inv = __fmul_rn(g, rsqrtf(__fadd_rn(v, 1e-5f)));
    float bz  = __fsub_rn(be, __fmul_rn(m, inv));
    if (inv > 0.0f) {
        int lo = -1025, hi = 1025, ans = 1 << 20;
        while (lo <= hi) {
            int mid = lo + ((hi - lo) >> 1);
            if (bnref((float)mid, b, inv, bz) >= 0.0f) { ans = mid; hi = mid - 1; }
            else lo = mid + 1;
        }
        *mu_out = 1; *T_out = ans;
    } else if (inv < 0.0f) {
        int lo = -1025, hi = 1025, ans = -(1 << 20);
        while (lo <= hi) {
            int mid = lo + ((hi - lo) >> 1);
            if (bnref((float)mid, b, inv, bz) >= 0.0f) { ans = mid; lo = mid + 1; }
            else hi = mid - 1;
        }
        *mu_out = -1; *T_out = -ans;
    } else {
        *mu_out = 0; *T_out = (bz >= 0.0f) ? -(1 << 20) : (1 << 20);
    }
}

// stage-B K values with sign-folded weight bits (round-11 form, proven):
__device__ void mk_k(float b, float g, float be, float m, float v,
                     int C0, int C1, int* K0, int* K1)
{
    float inv = __fmul_rn(g, rsqrtf(__fadd_rn(v, 1e-5f)));
    float bz  = __fsub_rn(be, __fmul_rn(m, inv));
    if (inv > 0.0f) {
        int lo = -1025, hi = 1025, ans = 1 << 20;
        while (lo <= hi) {
            int mid = lo + ((hi - lo) >> 1);
            if (bnref((float)mid, b, inv, bz) >= 0.0f) { ans = mid; hi = mid - 1; }
            else lo = mid + 1;
        }
        *K0 = (C0 - ans) >> 1; *K1 = (C1 - ans) >> 1;
    } else if (inv < 0.0f) {
        int lo = -1025, hi = 1025, ans = -(1 << 20);
        while (lo <= hi) {
            int mid = lo + ((hi - lo) >> 1);
            if (bnref((float)mid, b, inv, bz) >= 0.0f) { ans = mid; lo = mid + 1; }
            else hi = mid - 1;
        }
        *K0 = (C0 + ans) >> 1; *K1 = (C1 + ans) >> 1;
    } else {
        bool always = (bz >= 0.0f);
        *K0 = always ? C0 : -1; *K1 = always ? C1 : -1;
    }
}

__device__ __forceinline__ int musgn(float g) {
    return (g > 0.f) ? 1 : ((g < 0.f) ? -1 : 0);
}

__global__ void prep_kernel(
    const float* __restrict__ w1, const float* __restrict__ b1,
    const float* __restrict__ w2, const float* __restrict__ b2,
    const float* __restrict__ w3, const float* __restrict__ b3,
    const float* __restrict__ w4, const float* __restrict__ b4,
    const float* __restrict__ g1, const float* __restrict__ be1,
    const float* __restrict__ m1, const float* __restrict__ v1,
    const float* __restrict__ g2, const float* __restrict__ be2,
    const float* __restrict__ m2, const float* __restrict__ v2,
    const float* __restrict__ g3, const float* __restrict__ be3,
    const float* __restrict__ m3, const float* __restrict__ v3,
    const float* __restrict__ g4, const float* __restrict__ be4,
    const float* __restrict__ m4, const float* __restrict__ v4,
    const float* __restrict__ wf)
{
    const int NT = 288 + 32 + 64 + 128 + 128 + 256 + 640 + 24576 + 98304;
    for (int u0 = blockIdx.x * blockDim.x + threadIdx.x; u0 < NT;
         u0 += gridDim.x * blockDim.x) {
        int u = u0;
        if (u < 288) { g_w1s[u] = (w1[u] >= 0.f) ? 1.f : -1.f; continue; }
        u -= 288;
        if (u < 32) {
            int c = u;
            double inv = (double)g1[c] / sqrt((double)v1[c] + EPSBND);
            double bz  = (double)be1[c] - (double)m1[c] * inv;
            g_inv1d[c] = inv; g_bz1d[c] = bz; g_b1d[c] = (double)b1[c];
            g_p1[c] = make_float2((float)inv, (float)((double)b1[c] * inv + bz));
            continue;
        }
        u -= 32;
        if (u < 64) {
            int K0, K1;
            mk_k(b2[u], g2[u], be2[u], m2[u], v2[u], 96, 64, &K0, &K1);
            g_kB[u] = make_int2(K0, K1);
            continue;
        }
        u -= 64;
        if (u < 128) {
            int mu, T;
            mk_threshold(b3[u], g3[u], be3[u], m3[u], v3[u], &mu, &T);
            g_TC[u] = T;
            continue;
        }
        u -= 128;
        if (u < 128) {
            int mu, T;
            mk_threshold(b4[u], g4[u], be4[u], m4[u], v4[u], &mu, &T);
            g_TD[u] = T;
            continue;
        }
        u -= 128;
        if (u < 256) {                   // wb2 bits, sign-folded (t=3 pad)
            int c = u >> 2, t = u & 3;
            unsigned flip = (g2[c] < 0.f) ? 0xffffffffu : 0u;
            unsigned word = 0;
            if (t < 3) {
                for (int i = 0; i < 32; i++)
                    word |= (unsigned)(w2[c * 96 + i * 3 + t] >= 0.f) << i;
                word ^= flip;
            }
            g_wb2[u] = word;
            continue;
        }
        u -= 256;
        if (u < 640) {                   // wfb
            int o = u / 64, jw = u % 64;
            unsigned word = 0;
            for (int i = 0; i < 32; i++)
                word |= (unsigned)(wf[o * 2048 + jw * 32 + i] >= 0.f) << i;
            g_wfb[u] = word;
            continue;
        }
        u -= 640;
        if (u < 24576) {                 // wCb: [ch][k = tap*64 + cin]
            int c = u / 192, k = u % 192, tap = k >> 6, cin = k & 63;
            int mu = musgn(g3[c]);
            int sg = (w3[c * 192 + cin * 3 + tap] >= 0.f) ? 1 : -1;
            g_wCb[u] = (signed char)(mu * sg);
            continue;
        }
        u -= 24576;
        {                                // wDb: [ch][k = h*128 + cin]
            int c = u / 768, k = u % 768, h = k >> 7, cin = k & 127;
            int mu = musgn(g4[c]);
            int sg = (w4[c * 768 + cin * 6 + h] >= 0.f) ? 1 : -1;
            g_wDb[u] = (signed char)(mu * sg);
        }
    }
}

// Rare exact path (double, round-5 chain).
__device__ __noinline__ bool conv1_slow(const float* __restrict__ row, int L)
{
    double inv1 = g_inv1d[L], bz1 = g_bz1d[L], bb1 = g_b1d[L];
    double s0 = 0.0, s1 = 0.0;
#pragma unroll
    for (int t = 0; t < 9; t++) {
        double w = (double)g_w1s[L * 9 + t];
        s0 = fma(w, (double)row[t],     s0);
        s1 = fma(w, (double)row[t + 2], s1);
    }
    double y0 = (s0 + bb1) * inv1 + bz1;
    double y1 = (s1 + bb1) * inv1 + bz1;
    return (y0 >= 0.0) || (y1 >= 0.0);
}

__device__ __forceinline__ void mma_s8(int& c0, int& c1, int& c2, int& c3,
                                       unsigned a0, unsigned a1, unsigned a2,
                                       unsigned a3, unsigned b0, unsigned b1)
{
    asm("mma.sync.aligned.m16n8k32.row.col.s32.s8.s8.s32 "
        "{%0,%1,%2,%3}, {%4,%5,%6,%7}, {%8,%9}, {%0,%1,%2,%3};"
        : "+r"(c0), "+r"(c1), "+r"(c2), "+r"(c3)
        : "r"(a0), "r"(a1), "r"(a2), "r"(a3), "r"(b0), "r"(b1));
}

// ---------------------------------------------------------------------------
// Main fused kernel: 1 block = 1 sample, 128 threads (4 warps).
// ---------------------------------------------------------------------------
__global__ __launch_bounds__(128)
void bcnn_kernel(const float* __restrict__ x, const float* __restrict__ bf,
                 float* __restrict__ out)
{
    const int b   = blockIdx.x;
    const int tid = threadIdx.x;
    const int W   = tid >> 5;
    const int L   = tid & 31;
    const int g   = L >> 2;      // mma group (row) id
    const int q   = L & 3;       // mma thread-in-group

    __shared__ __align__(16) float       xs[6 * 136];
    __shared__ __align__(16) unsigned    b1s[192];
    __shared__ __align__(16) signed char act[6 * 34 * 64];   // +-1 bytes, pads
    __shared__ __align__(16) signed char b3a[96 * 144];      // +-1 bytes
    __shared__ __align__(16) unsigned char d4[2048];
    __shared__ __align__(16) unsigned    fcw[64];

    // load sample with zero padding + zero act pad columns (w idx 0 and 33)
    const float* xb = x + (size_t)b * 768;
    for (int i = tid; i < 768; i += 128) {
        int r = i >> 7, c = i & 127;
        xs[r * 136 + 4 + c] = xb[i];
    }
    if (tid < 48) {
        int r = tid >> 3, j = tid & 7;
        xs[r * 136 + ((j < 4) ? j : (j + 128))] = 0.f;
    }
    for (int i = tid; i < 192; i += 128) {     // 6 rows x 2 pad cols x 16 words
        int h = i / 32, j = i % 32;
        int w0 = (j < 16) ? j : (33 * 16 + (j - 16));
        ((unsigned*)act)[h * 544 + w0] = 0;
    }

    // ---- stage A: conv1 + bias + bn + pool(w2) + binarize -> b1s bits ----
    float wrf[9];
#pragma unroll
    for (int t = 0; t < 9; t++) wrf[t] = g_w1s[L * 9 + t];
    float2 p1 = g_p1[L];
    __syncthreads();

    for (int pos = W; pos < 192; pos += 4) {
        int h = pos >> 5, wp = pos & 31;
        const float* row = xs + h * 136 + 4 * wp;
        const float4* rv = (const float4*)row;
        float4 v0 = rv[0], v1 = rv[1], v2 = rv[2];
        float s0, s1;
        s0 = wrf[0] * v0.x;
        s0 = __fmaf_rn(wrf[1], v0.y, s0);
        s0 = __fmaf_rn(wrf[2], v0.z, s0);
        s0 = __fmaf_rn(wrf[3], v0.w, s0);
        s0 = __fmaf_rn(wrf[4], v1.x, s0);
        s0 = __fmaf_rn(wrf[5], v1.y, s0);
        s0 = __fmaf_rn(wrf[6], v1.z, s0);
        s0 = __fmaf_rn(wrf[7], v1.w, s0);
        s0 = __fmaf_rn(wrf[8], v2.x, s0);
        s1 = wrf[0] * v0.z;
        s1 = __fmaf_rn(wrf[1], v0.w, s1);
        s1 = __fmaf_rn(wrf[2], v1.x, s1);
        s1 = __fmaf_rn(wrf[3], v1.y, s1);
        s1 = __fmaf_rn(wrf[4], v1.z, s1);
        s1 = __fmaf_rn(wrf[5], v1.w, s1);
        s1 = __fmaf_rn(wrf[6], v2.x, s1);
        s1 = __fmaf_rn(wrf[7], v2.y, s1);
        s1 = __fmaf_rn(wrf[8], v2.z, s1);
        float ym = fmaxf(__fmaf_rn(s0, p1.x, p1.y), __fmaf_rn(s1, p1.x, p1.y));
        bool bit = (ym >= 0.f);
        if (fabsf(ym) < BAND) bit = conv1_slow(row, L);
        b1s[pos] = __ballot_sync(0xffffffffu, bit);
    }
    __syncthreads();

    // ---- stage B: conv2 popc -> +-1 bytes act[h][w+1][c] (no ballots) ----
    {
        int q2 = W & 1;
        int c = q2 * 32 + L;
        uint4 wt = *(const uint4*)&g_wb2[c * 4];
        int2 kb = g_kB[c];
        int K96 = kb.x, K64 = kb.y;
        int r0 = 3 * (W >> 1);
        for (int r = r0; r < r0 + 3; r++) {
            const unsigned* rp = b1s + r * 32;
            signed char* op = act + r * 2176 + 64 + c;    // w stride = 64
            uint4 A = *(const uint4*)rp;
            op[0]   = (__popc(A.x^wt.y)+__popc(A.y^wt.z) <= K64) ? 1 : -1;
            op[64]  = (__popc(A.x^wt.x)+__popc(A.y^wt.y)+__popc(A.z^wt.z) <= K96) ? 1 : -1;
            op[128] = (__popc(A.y^wt.x)+__popc(A.z^wt.y)+__popc(A.w^wt.z) <= K96) ? 1 : -1;
            unsigned p2 = A.z, p3 = A.w;
#pragma unroll
            for (int k2 = 1; k2 < 8; k2++) {
                A = *(const uint4*)(rp + 4 * k2);
                op[(4*k2-1)*64] = (__popc(p2 ^wt.x)+__popc(p3 ^wt.y)+__popc(A.x^wt.z) <= K96) ? 1 : -1;
                op[(4*k2  )*64] = (__popc(p3 ^wt.x)+__popc(A.x^wt.y)+__popc(A.y^wt.z) <= K96) ? 1 : -1;
                op[(4*k2+1)*64] = (__popc(A.x^wt.x)+__popc(A.y^wt.y)+__popc(A.z^wt.z) <= K96) ? 1 : -1;
                op[(4*k2+2)*64] = (__popc(A.y^wt.x)+__popc(A.z^wt.y)+__popc(A.w^wt.z) <= K96) ? 1 : -1;
                p2 = A.z; p3 = A.w;
            }
            op[31*64] = (__popc(p2^wt.x)+__popc(p3^wt.y) <= K64) ? 1 : -1;
        }
    }
    __syncthreads();

    // ---- stage C: conv3+pool via IMMA; M=pos(16/tile), N=ch, K=192 ----
    {
        for (int mi = 0; mi < 3; mi++) {
            int m = W + mi * 4;                 // mtile 0..11
            int h = m >> 1, half = m & 1;
            // K window of output position w starts at padded row w:
            const signed char* rb0 = act + h * 2176 + (half * 16 + g) * 64 + 4 * q;
            const signed char* rb1 = rb0 + 8 * 64;
            unsigned a[6][4];
#pragma unroll
            for (int ks = 0; ks < 6; ks++) {
                a[ks][0] = *(const unsigned*)(rb0 + ks * 32);
                a[ks][1] = *(const unsigned*)(rb1 + ks * 32);
                a[ks][2] = *(const unsigned*)(rb0 + ks * 32 + 16);
                a[ks][3] = *(const unsigned*)(rb1 + ks * 32 + 16);
            }
            for (int nt = 0; nt < 16; nt++) {
                const signed char* wb = g_wCb + (nt * 8 + g) * 192 + 4 * q;
                int c0 = 0, c1 = 0, c2 = 0, c3 = 0;
#pragma unroll
                for (int ks = 0; ks < 6; ks++) {
                    unsigned b0  = *(const unsigned*)(wb + ks * 32);
                    unsigned b1v = *(const unsigned*)(wb + ks * 32 + 16);
                    mma_s8(c0, c1, c2, c3,
                           a[ks][0], a[ks][1], a[ks][2], a[ks][3], b0, b1v);
                }
                int T0 = g_TC[nt * 8 + 2 * q], T1 = g_TC[nt * 8 + 2 * q + 1];
                int p0  = max(c0, __shfl_xor_sync(0xffffffffu, c0, 4));
                int p1v = max(c1, __shfl_xor_sync(0xffffffffu, c1, 4));
                int p2  = max(c2, __shfl_xor_sync(0xffffffffu, c2, 4));
                int p3  = max(c3, __shfl_xor_sync(0xffffffffu, c3, 4));
                if ((g & 1) == 0) {
                    int pp = h * 16 + half * 8 + (g >> 1);
                    signed char* o = b3a + pp * 144 + nt * 8 + 2 * q;
                    o[0]       = (p0  >= T0) ? 1 : -1;
                    o[1]       = (p1v >= T1) ? 1 : -1;
                    o[4*144]   = (p2  >= T0) ? 1 : -1;
                    o[4*144+1] = (p3  >= T1) ? 1 : -1;
                }
            }
        }
    }
    __syncthreads();

    // ---- stage D: conv4 via IMMA; M=16 pos, N=128 ch, K=768 ----
    {
        int acc[4][4];
#pragma unroll
        for (int i = 0; i < 4; i++)
#pragma unroll
            for (int j = 0; j < 4; j++) acc[i][j] = 0;
#pragma unroll 4
        for (int ks = 0; ks < 24; ks++) {
            int h = ks >> 2, cb = (ks & 3) * 32;
            const signed char* rb0 = b3a + (h * 16 + g) * 144 + cb + 4 * q;
            const signed char* rb1 = rb0 + 8 * 144;
            unsigned a0 = *(const unsigned*)rb0;
            unsigned a1 = *(const unsigned*)rb1;
            unsigned a2 = *(const unsigned*)(rb0 + 16);
            unsigned a3 = *(const unsigned*)(rb1 + 16);
#pragma unroll
            for (int i = 0; i < 4; i++) {
                int nt = W * 4 + i;
                const signed char* wb = g_wDb + (nt * 8 + g) * 768 + ks * 32 + 4 * q;
                unsigned b0  = *(const unsigned*)wb;
                unsigned b1v = *(const unsigned*)(wb + 16);
                mma_s8(acc[i][0], acc[i][1], acc[i][2], acc[i][3],
                       a0, a1, a2, a3, b0, b1v);
            }
        }
#pragma unroll
        for (int i = 0; i < 4; i++) {
            int nt = W * 4 + i, ch0 = nt * 8 + 2 * q;
            int T0 = g_TD[ch0], T1 = g_TD[ch0 + 1];
            d4[ch0 * 16 + g]           = (acc[i][0] >= T0);
            d4[(ch0 + 1) * 16 + g]     = (acc[i][1] >= T1);
            d4[ch0 * 16 + g + 8]       = (acc[i][2] >= T0);
            d4[(ch0 + 1) * 16 + g + 8] = (acc[i][3] >= T1);
        }
    }
    __syncthreads();

    // ---- pack fc input bits: word jw bit i = d4[jw*32 + i] (k = ch*16+w) ----
    for (int t = 0; t < 16; t++) {
        int jw = W * 16 + t;
        fcw[jw] = __ballot_sync(0xffffffffu, d4[jw * 32 + L] != 0);
    }
    __syncthreads();

    // ---- stage E: fc (10 x 2048 binary dot) + bf ----
    {
        unsigned f0 = fcw[L], f1 = fcw[32 + L];
        for (int o = W; o < 10; o += 4) {
            int s = __popc(f0 ^ g_wfb[o * 64 + L])
                  + __popc(f1 ^ g_wfb[o * 64 + 32 + L]);
            int tot = __reduce_add_sync(0xffffffffu, s);
            if (L == 0) out[(size_t)b * 10 + o] = (float)(2048 - 2 * tot) + bf[o];
        }
    }
}

extern "C" void kernel_launch(void* const* d_in, const int* in_sizes, int n_in,
                              void* d_out, int out_size)
{
    const float* x   = (const float*)d_in[0];
    const float* w1  = (const float*)d_in[1];
    const float* b1  = (const float*)d_in[2];
    const float* w2  = (const float*)d_in[3];
    const float* b2  = (const float*)d_in[4];
    const float* w3  = (const float*)d_in[5];
    const float* b3  = (const float*)d_in[6];
    const float* w4  = (const float*)d_in[7];
    const float* b4  = (const float*)d_in[8];
    const float* g1  = (const float*)d_in[9];
    const float* be1 = (const float*)d_in[10];
    const float* m1  = (const float*)d_in[11];
    const float* v1  = (const float*)d_in[12];
    const float* g2  = (const float*)d_in[13];
    const float* be2 = (const float*)d_in[14];
    const float* m2  = (const float*)d_in[15];
    const float* v2  = (const float*)d_in[16];
    const float* g3  = (const float*)d_in[17];
    const float* be3 = (const float*)d_in[18];
    const float* m3  = (const float*)d_in[19];
    const float* v3  = (const float*)d_in[20];
    const float* g4  = (const float*)d_in[21];
    const float* be4 = (const float*)d_in[22];
    const float* m4  = (const float*)d_in[23];
    const float* v4  = (const float*)d_in[24];
    const float* wf  = (const float*)d_in[25];
    const float* bf  = (const float*)d_in[26];

    int B = in_sizes[0] / 768;

    prep_kernel<<<128, 256>>>(w1, b1, w2, b2, w3, b3, w4, b4,
                              g1, be1, m1, v1, g2, be2, m2, v2,
                              g3, be3, m3, v3, g4, be4, m4, v4, wf);
    bcnn_kernel<<<B, 128>>>(x, bf, (float*)d_out);
}